// round 16
// baseline (speedup 1.0000x reference)
#include <cuda_runtime.h>
#include <cuda_fp16.h>
#include <math.h>
#include <stdint.h>

#define N_V 10000
#define NSPEC 64
#define IN_DESC 352
#define OUT_DESC 256

// ---------------- scratch (device globals; no allocations allowed) ----------
__device__ float g_acc[N_V * 256];   // accA (pre-BN, max width 256)
__device__ float g_h[N_V * 128];     // accB (pre-BN, width <=128)
__device__ float g_Gc0[4 * 4096];    // [G | c0_layer1 | c0_layer2 | c0_layer3]
__device__ float g_stats[5 * 512];   // per-layer [sum(256) | sumsq(256)]
__device__ float g_U[64 * 128];      // spectral weight combo [64,Cout]
__device__ float g_Wx[64 * 128];     // direct-X weight combo [64,Cout]
__device__ __half g_bw[N_V * 256];   // fc3_w transposed [N,K] fp16
__device__ __half g_aw[N_V * 256];   // desc [M,K] fp16

// ---------------- mma.sync + cp.async helpers (base sm_103-legal) -----------
__device__ __forceinline__ uint32_t smem_u32(const void* p) {
    uint32_t a;
    asm("{ .reg .u64 t; cvta.to.shared.u64 t, %1; cvt.u32.u64 %0, t; }" : "=r"(a) : "l"(p));
    return a;
}
#define LDSM_X4(r0, r1, r2, r3, addr) \
    asm volatile("ldmatrix.sync.aligned.m8n8.x4.shared.b16 {%0,%1,%2,%3}, [%4];" \
        : "=r"(r0), "=r"(r1), "=r"(r2), "=r"(r3) : "r"(addr))
#define LDSM_X2(r0, r1, addr) \
    asm volatile("ldmatrix.sync.aligned.m8n8.x2.shared.b16 {%0,%1}, [%2];" \
        : "=r"(r0), "=r"(r1) : "r"(addr))
#define MMA_F16(c, a, b) \
    asm volatile("mma.sync.aligned.m16n8k16.row.col.f32.f16.f16.f32 " \
        "{%0,%1,%2,%3}, {%4,%5,%6,%7}, {%8,%9}, {%0,%1,%2,%3};" \
        : "+f"((c)[0]), "+f"((c)[1]), "+f"((c)[2]), "+f"((c)[3]) \
        : "r"((a)[0]), "r"((a)[1]), "r"((a)[2]), "r"((a)[3]), "r"((b)[0]), "r"((b)[1]))
#define CP_ASYNC16(smaddr, gptr) \
    asm volatile("cp.async.cg.shared.global [%0], [%1], 16;" :: "r"(smaddr), "l"(gptr))
#define CP_COMMIT() asm volatile("cp.async.commit_group;" ::: "memory")
#define CP_WAIT1()  asm volatile("cp.async.wait_group 1;" ::: "memory")
#define CP_WAIT0()  asm volatile("cp.async.wait_group 0;" ::: "memory")

__device__ __forceinline__ uint32_t sw128(uint32_t off) {
    return off ^ ((off >> 3) & 0x70);
}
__device__ __forceinline__ uint32_t packh(__half a, __half b) {
    unsigned short ua = *reinterpret_cast<unsigned short*>(&a);
    unsigned short ub = *reinterpret_cast<unsigned short*>(&b);
    return (uint32_t)ua | ((uint32_t)ub << 16);
}
__device__ __forceinline__ float bnr(float x, float sc, float sh) {
    return fmaxf(fmaf(x, sc, sh), 0.f);
}
// BN scale/shift from accumulated sums
__device__ __forceinline__ float2 bn_coef(float sum, float sq, float gam, float bet) {
    float mean = sum * (1.f / N_V);
    float var = sq * (1.f / N_V) - mean * mean;
    float sc = gam * rsqrtf(var + 1e-3f);
    return make_float2(sc, bet - mean * sc);
}

// FMA-pipe exp
__device__ __forceinline__ float fexp(float x) {
    float y = fmaxf(x * 1.4426950408889634f, -120.f);
    float fi = floorf(y);
    float f = y - fi;
    float r = 1.5403530e-4f;
    r = fmaf(r, f, 1.3333558e-3f);
    r = fmaf(r, f, 9.6181291e-3f);
    r = fmaf(r, f, 5.5504109e-2f);
    r = fmaf(r, f, 2.4022651e-1f);
    r = fmaf(r, f, 6.9314718e-1f);
    r = fmaf(r, f, 1.0f);
    return __int_as_float(__float_as_int(r) + ((int)fi << 23));
}

// ---------------- zero G/c0 arena + stats ------------------------------------
__global__ void zeroall() {
    int i = blockIdx.x * 256 + threadIdx.x;
    if (i < 4 * 4096) g_Gc0[i] = 0.f;
    else if (i < 4 * 4096 + 5 * 512) g_stats[i - 4 * 4096] = 0.f;
}

// ---------------- fc3_w pre-transpose + fp16 ---------------------------------
__global__ void split_b_kernel(const float* __restrict__ W) {
    __shared__ float s[32][33];
    const int tx = threadIdx.x, ty = threadIdx.y;
    const int n0 = blockIdx.x * 32, k0 = blockIdx.y * 32;
    float v = 0.f;
    if (n0 + tx < N_V) v = W[(size_t)(k0 + ty) * N_V + n0 + tx];
    s[ty][tx] = v;
    __syncthreads();
    int n = n0 + ty;
    if (n < N_V) g_bw[(size_t)n * 256 + k0 + tx] = __float2half(s[tx][ty]);
}

// ---------------- fc3 GEMM: mma.sync fp16, cp.async double-buffered ----------
#define SM_A0 0
#define SM_B0 16384
#define SM_A1 32768
#define SM_B1 49152
#define SM_TOT 65536

__global__ __launch_bounds__(256, 2)
void fc3_kernel(const float* __restrict__ bias, float* __restrict__ C) {
    extern __shared__ char smem[];
    const uint32_t sbase = smem_u32(smem);
    const int tid = threadIdx.x;
    const int wid = tid >> 5, lane = tid & 31;
    const int wm = wid >> 2, wn = wid & 3;
    const int row0 = blockIdx.y * 128, col0 = blockIdx.x * 128;

    float acc[4][4][4] = {};

    const int l15 = lane & 15;
    const uint32_t a_row = (uint32_t)(wm * 64 + l15);
    const uint32_t a_halfb = (uint32_t)((lane >> 4) * 16);
    const uint32_t b_row = (uint32_t)(wn * 32 + (l15 & 7));
    const uint32_t b_halfb = (uint32_t)((l15 >> 3) * 16);

    const int lr = tid >> 3, lc = tid & 7;

    auto load_chunk = [&](int kc, int buf) {
        const uint32_t sa = sbase + (buf ? SM_A1 : SM_A0);
        const uint32_t sb = sbase + (buf ? SM_B1 : SM_B0);
        #pragma unroll
        for (int t = 0; t < 4; t++) {
            int r = lr + t * 32;
            uint32_t soff = sw128((uint32_t)(r * 128 + lc * 16));
            int ra = min(row0 + r, N_V - 1);
            const char* ga = (const char*)g_aw + (size_t)ra * 512 + (size_t)kc * 128 + lc * 16;
            CP_ASYNC16(sa + soff, ga);
            int rb = min(col0 + r, N_V - 1);
            const char* gb = (const char*)g_bw + (size_t)rb * 512 + (size_t)kc * 128 + lc * 16;
            CP_ASYNC16(sb + soff, gb);
        }
    };

    load_chunk(0, 0);
    CP_COMMIT();

    #pragma unroll
    for (int kc = 0; kc < 4; kc++) {
        if (kc < 3) {
            load_chunk(kc + 1, (kc + 1) & 1);
            CP_COMMIT();
            CP_WAIT1();
        } else {
            CP_WAIT0();
        }
        __syncthreads();
        const uint32_t sa = sbase + ((kc & 1) ? SM_A1 : SM_A0);
        const uint32_t sb = sbase + ((kc & 1) ? SM_B1 : SM_B0);
        #pragma unroll
        for (int ks = 0; ks < 4; ks++) {
            uint32_t af[4][4], bf[4][2];
            #pragma unroll
            for (int mt = 0; mt < 4; mt++) {
                uint32_t off = sw128((a_row + mt * 16) * 128 + ks * 32 + a_halfb);
                LDSM_X4(af[mt][0], af[mt][1], af[mt][2], af[mt][3], sa + off);
            }
            #pragma unroll
            for (int nt = 0; nt < 4; nt++) {
                uint32_t off = sw128((b_row + nt * 8) * 128 + ks * 32 + b_halfb);
                LDSM_X2(bf[nt][0], bf[nt][1], sb + off);
            }
            #pragma unroll
            for (int mt = 0; mt < 4; mt++)
                #pragma unroll
                for (int nt = 0; nt < 4; nt++)
                    MMA_F16(acc[mt][nt], af[mt], bf[nt]);
        }
        __syncthreads();
    }

    const int r_base = row0 + wm * 64 + (lane >> 2);
    const int c_base = col0 + wn * 32 + ((lane & 3) << 1);
    #pragma unroll
    for (int mt = 0; mt < 4; mt++) {
        #pragma unroll
        for (int nt = 0; nt < 4; nt++) {
            int cc = c_base + nt * 8;
            if (cc >= N_V) continue;
            float2 bb = *(const float2*)(bias + cc);
            int rr = r_base + mt * 16;
            if (rr < N_V) {
                float2 v = make_float2(acc[mt][nt][0] + bb.x, acc[mt][nt][1] + bb.y);
                *(float2*)(C + (size_t)rr * N_V + cc) = v;
            }
            if (rr + 8 < N_V) {
                float2 v = make_float2(acc[mt][nt][2] + bb.x, acc[mt][nt][3] + bb.y);
                *(float2*)(C + (size_t)(rr + 8) * N_V + cc) = v;
            }
        }
    }
}

// ---------------- small GEMM (fc1/fc2): C = BN?(A) @ B, + stats --------------
// BM in {32, 64}: M-tile rows (32 doubles grid for grid-starved fc1).
template<int BNIN, int STATS, int BM>
__global__ void gemm_small(const float* __restrict__ A, const float* __restrict__ B,
                           float* __restrict__ C, int M, int Nn, int K,
                           const float* __restrict__ stIn,
                           const float* __restrict__ gamIn, const float* __restrict__ betIn,
                           float* __restrict__ stOut) {
    constexpr int TM = BM / 16;
    __shared__ float As[16][BM];
    __shared__ float Bs[16][64];
    __shared__ float sSc[128], sSh[128];
    __shared__ float sbuf[BM * 65 + 2 * 4 * 64];
    const int tid = threadIdx.x;
    const int ty = tid >> 4, tx = tid & 15;
    const int row0 = blockIdx.y * BM, col0 = blockIdx.x * 64;
    const int arow = tid >> 2, ak = (tid & 3) << 2;
    const int bk = tid >> 4, bcol = (tid & 15) << 2;
    if (BNIN && tid < 128) {
        float2 cs = bn_coef(stIn[tid], stIn[256 + tid], gamIn[tid], betIn[tid]);
        sSc[tid] = cs.x; sSh[tid] = cs.y;
    }
    if (BNIN) __syncthreads();
    float acc[TM][4] = {};
    for (int k0 = 0; k0 < K; k0 += 16) {
        if (BM == 64 || tid < 128) {
            float4 av = make_float4(0.f, 0.f, 0.f, 0.f);
            if (row0 + arow < M)
                av = *(const float4*)(A + (size_t)(row0 + arow) * K + k0 + ak);
            if (BNIN) {
                av.x = bnr(av.x, sSc[k0 + ak + 0], sSh[k0 + ak + 0]);
                av.y = bnr(av.y, sSc[k0 + ak + 1], sSh[k0 + ak + 1]);
                av.z = bnr(av.z, sSc[k0 + ak + 2], sSh[k0 + ak + 2]);
                av.w = bnr(av.w, sSc[k0 + ak + 3], sSh[k0 + ak + 3]);
            }
            As[ak + 0][arow] = av.x; As[ak + 1][arow] = av.y;
            As[ak + 2][arow] = av.z; As[ak + 3][arow] = av.w;
        }
        float4 bv = *(const float4*)(B + (size_t)(k0 + bk) * Nn + col0 + bcol);
        *(float4*)(&Bs[bk][bcol]) = bv;
        __syncthreads();
        #pragma unroll
        for (int kk = 0; kk < 16; kk++) {
            float a[TM], b[4];
            #pragma unroll
            for (int i = 0; i < TM; i++) a[i] = As[kk][ty * TM + i];
            #pragma unroll
            for (int j = 0; j < 4; j++) b[j] = Bs[kk][tx * 4 + j];
            #pragma unroll
            for (int i = 0; i < TM; i++)
                #pragma unroll
                for (int j = 0; j < 4; j++)
                    acc[i][j] += a[i] * b[j];
        }
        __syncthreads();
    }
    #pragma unroll
    for (int i = 0; i < TM; i++) {
        int r = row0 + ty * TM + i;
        if (r >= M) continue;
        #pragma unroll
        for (int j = 0; j < 4; j++)
            C[(size_t)r * Nn + col0 + tx * 4 + j] = acc[i][j];
    }
    if (STATS) {
        #pragma unroll
        for (int i = 0; i < TM; i++)
            #pragma unroll
            for (int j = 0; j < 4; j++)
                sbuf[(ty * TM + i) * 65 + tx * 4 + j] = acc[i][j];
        __syncthreads();
        constexpr int RPC = BM / 4;
        const int c = tid & 63, chunk = tid >> 6;   // 4 chunks x RPC rows
        float s = 0.f, s2 = 0.f;
        #pragma unroll
        for (int rr = 0; rr < RPC; rr++) {
            int r = chunk * RPC + rr;
            if (row0 + r < M) {
                float v = sbuf[r * 65 + c];
                s += v; s2 += v * v;
            }
        }
        float* red = sbuf + BM * 65;
        red[chunk * 64 + c] = s;
        red[256 + chunk * 64 + c] = s2;
        __syncthreads();
        if (tid < 64) {
            float ts = 0.f, ts2 = 0.f;
            #pragma unroll
            for (int k = 0; k < 4; k++) { ts += red[k * 64 + tid]; ts2 += red[256 + k * 64 + tid]; }
            atomicAdd(&stOut[col0 + tid], ts);
            atomicAdd(&stOut[256 + col0 + tid], ts2);
        }
    }
}

// ---------------- 64x64 split-K reduce: out += D @ BN?(Z) --------------------
template<int BNIN>
__global__ void dmat_kernel(const float* __restrict__ Dm, const float* __restrict__ Z,
                            float* __restrict__ outp,
                            const float* __restrict__ stIn,
                            const float* __restrict__ gamIn, const float* __restrict__ betIn) {
    __shared__ float sD[4][64];
    __shared__ float sZ[4][64];
    const int tid = threadIdx.x;
    const int i4 = (tid >> 4) << 2;
    const int j4 = (tid & 15) << 2;
    const int zc = tid & 63;
    float zsc = 0.f, zsh = 0.f;
    if (BNIN) {
        float2 cs = bn_coef(stIn[zc], stIn[256 + zc], gamIn[zc], betIn[zc]);
        zsc = cs.x; zsh = cs.y;
    }
    float acc[4][4] = {};
    const int nb0 = blockIdx.x * 80;
    for (int nb = 0; nb < 80; nb += 4) {
        const int nbase = nb0 + nb;
        {
            int ii = tid >> 2, nn = tid & 3;
            sD[nn][ii] = Dm[(size_t)ii * N_V + nbase + nn];
            float z = Z[(size_t)(nbase + (tid >> 6)) * 64 + zc];
            if (BNIN) z = bnr(z, zsc, zsh);
            sZ[tid >> 6][zc] = z;
        }
        __syncthreads();
        #pragma unroll
        for (int nn = 0; nn < 4; nn++) {
            float d[4], z[4];
            #pragma unroll
            for (int a = 0; a < 4; a++) d[a] = sD[nn][i4 + a];
            #pragma unroll
            for (int b = 0; b < 4; b++) z[b] = sZ[nn][j4 + b];
            #pragma unroll
            for (int a = 0; a < 4; a++)
                #pragma unroll
                for (int b = 0; b < 4; b++)
                    acc[a][b] += d[a] * z[b];
        }
        __syncthreads();
    }
    #pragma unroll
    for (int a = 0; a < 4; a++)
        #pragma unroll
        for (int b = 0; b < 4; b++)
            atomicAdd(&outp[(i4 + a) * 64 + j4 + b], acc[a][b]);
}

// ---------------- spectral Chebyshev recurrence (one block, 1024 thr) --------
template<int COUT>
__global__ void spectral_kernel(const float* __restrict__ W,
                                const float* __restrict__ eigs,
                                const float* __restrict__ c0g) {
    extern __shared__ float sm[];
    float* G    = sm;
    float* c0   = G + 4096;
    float* bufA = c0 + 4096;
    float* bufB = bufA + 4096;
    float* ck   = bufB + 4096;
    float* U    = ck + 4096;
    float* sW   = U + 64 * COUT;
    __shared__ float e[64];
    const int tid = threadIdx.x;
    const int T = blockDim.x;
    for (int i = tid; i < 4096; i += T) { G[i] = g_Gc0[i]; c0[i] = c0g[i]; }
    if (tid < 64) e[tid] = eigs[tid];
    __syncthreads();
    for (int i = tid; i < 4096; i += T) { bufA[i] = 0.f; bufB[i] = e[i >> 6] * c0[i]; }
    for (int i = tid; i < 64 * COUT; i += T) sW[i] = W[64 * COUT + i];
    __syncthreads();
    for (int i = tid; i < 64 * COUT; i += T) {
        int r = i / COUT, c = i % COUT;
        float s = 0.f;
        #pragma unroll
        for (int m = 0; m < 64; m += 4) {
            float4 b4 = *(const float4*)(bufB + r * 64 + m);
            s += b4.x * sW[m * COUT + c] + b4.y * sW[(m + 1) * COUT + c]
               + b4.z * sW[(m + 2) * COUT + c] + b4.w * sW[(m + 3) * COUT + c];
        }
        U[i] = s;
    }
    float* sp = bufA;
    float* sc = bufB;
    for (int k = 1; k <= 4; k++) {
        __syncthreads();
        const float a = (k == 2) ? -1.f : ((k == 4) ? 1.f : 0.f);
        for (int i = tid; i < 4096; i += T) {
            int r = i >> 6, c = i & 63;
            float s = 0.f;
            #pragma unroll
            for (int m = 0; m < 64; m += 4) {
                float4 g4 = *(const float4*)(G + r * 64 + m);
                s += g4.x * sc[m * 64 + c] + g4.y * sc[(m + 1) * 64 + c]
                   + g4.z * sc[(m + 2) * 64 + c] + g4.w * sc[(m + 3) * 64 + c];
            }
            ck[i] = s + a * c0[i];
        }
        __syncthreads();
        for (int i = tid; i < 4096; i += T) sp[i] = 2.f * e[i >> 6] * ck[i] - sp[i];
        for (int i = tid; i < 64 * COUT; i += T) sW[i] = W[(size_t)(k + 1) * 64 * COUT + i];
        __syncthreads();
        for (int i = tid; i < 64 * COUT; i += T) {
            int r = i / COUT, c = i % COUT;
            float s = 0.f;
            #pragma unroll
            for (int m = 0; m < 64; m += 4) {
                float4 p4 = *(const float4*)(sp + r * 64 + m);
                s += p4.x * sW[m * COUT + c] + p4.y * sW[(m + 1) * COUT + c]
                   + p4.z * sW[(m + 2) * COUT + c] + p4.w * sW[(m + 3) * COUT + c];
            }
            U[i] += s;
        }
        float* t = sp; sp = sc; sc = t;
    }
    __syncthreads();
    for (int i = tid; i < 64 * COUT; i += T) {
        g_U[i] = U[i];
        g_Wx[i] = W[i] - W[2 * 64 * COUT + i] + W[4 * 64 * COUT + i];
    }
}

// ---------------- cheb output: out = BN(X) @ Wx + V @ U, + stats -------------
// ROWS=64 per CTA (grid 157 for both COUT), 4 threads per row.
template<int COUT>
__global__ void chebout_kernel(const float* __restrict__ X, const float* __restrict__ Vm,
                               float* __restrict__ outp,
                               const float* __restrict__ stIn,
                               const float* __restrict__ gamIn, const float* __restrict__ betIn,
                               float* __restrict__ stOut) {
    constexpr int ROWS = 64;
    constexpr int CPT = COUT / 4;        // columns per thread
    constexpr int CH = 256 / COUT;
    constexpr int STRIDE = COUT + 1;
    extern __shared__ float sm[];
    float* sWx = sm;
    float* sU  = sWx + 64 * COUT;
    float* sX  = sU + 64 * COUT;
    float* sV  = sX + ROWS * 64;
    __shared__ float sSc[64], sSh[64];
    const int tid = threadIdx.x;
    if (tid < 64) {
        float2 cs = bn_coef(stIn[tid], stIn[256 + tid], gamIn[tid], betIn[tid]);
        sSc[tid] = cs.x; sSh[tid] = cs.y;
    }
    __syncthreads();
    for (int i = tid; i < 64 * COUT; i += 256) { sWx[i] = g_Wx[i]; sU[i] = g_U[i]; }
    const int row0 = blockIdx.x * ROWS;
    for (int i = tid; i < ROWS * 16; i += 256) {
        int r = i >> 4, q = i & 15;
        int gr = row0 + r;
        float4 xv = make_float4(0.f, 0.f, 0.f, 0.f), vv = xv;
        if (gr < N_V) {
            xv = *(const float4*)(X + (size_t)gr * 64 + q * 4);
            vv = *(const float4*)(Vm + (size_t)gr * 64 + q * 4);
            xv.x = bnr(xv.x, sSc[q * 4 + 0], sSh[q * 4 + 0]);
            xv.y = bnr(xv.y, sSc[q * 4 + 1], sSh[q * 4 + 1]);
            xv.z = bnr(xv.z, sSc[q * 4 + 2], sSh[q * 4 + 2]);
            xv.w = bnr(xv.w, sSc[q * 4 + 3], sSh[q * 4 + 3]);
        }
        *(float4*)(sX + r * 64 + q * 4) = xv;
        *(float4*)(sV + r * 64 + q * 4) = vv;
    }
    __syncthreads();
    const int lr = tid >> 2;             // row 0..63
    const int j0 = (tid & 3) * CPT;
    const int gr = row0 + lr;
    float acc[CPT] = {};
    #pragma unroll 4
    for (int k = 0; k < 64; k++) {
        float a = sX[lr * 64 + k];
        #pragma unroll
        for (int j = 0; j < CPT; j++) acc[j] += a * sWx[k * COUT + j0 + j];
    }
    #pragma unroll 4
    for (int k = 0; k < 64; k++) {
        float v = sV[lr * 64 + k];
        #pragma unroll
        for (int j = 0; j < CPT; j++) acc[j] += v * sU[k * COUT + j0 + j];
    }
    if (gr < N_V) {
        float* o = outp + (size_t)gr * COUT + j0;
        #pragma unroll
        for (int j = 0; j < CPT; j++) o[j] = acc[j];
    }
    // ---- stats epilogue: per-column sum/sumsq over this block's rows ----
    __syncthreads();               // done reading sWx/sU/sX/sV; reuse sm
    float* sbuf = sm;              // ROWS*STRIDE floats
    #pragma unroll
    for (int j = 0; j < CPT; j++) sbuf[lr * STRIDE + j0 + j] = acc[j];
    __syncthreads();
    {
        const int c = tid % COUT, chunk = tid / COUT;   // CH chunks x RPC rows
        constexpr int RPC = ROWS / CH;
        float s = 0.f, s2 = 0.f;
        #pragma unroll
        for (int rr = 0; rr < RPC; rr++) {
            int r = chunk * RPC + rr;
            if (row0 + r < N_V) {
                float v = sbuf[r * STRIDE + c];
                s += v; s2 += v * v;
            }
        }
        float* red = sbuf + ROWS * STRIDE;
        red[chunk * COUT + c] = s;
        red[CH * COUT + chunk * COUT + c] = s2;
        __syncthreads();
        if (tid < COUT) {
            float ts = 0.f, ts2 = 0.f;
            #pragma unroll
            for (int k = 0; k < CH; k++) {
                ts += red[k * COUT + tid];
                ts2 += red[CH * COUT + k * COUT + tid];
            }
            atomicAdd(&stOut[tid], ts);
            atomicAdd(&stOut[256 + tid], ts2);
        }
    }
}

// ---------------- final BN apply -> desc fp32 + fp16 -------------------------
__global__ void bn_apply_desc(const float* __restrict__ X, float* __restrict__ desc,
                              const float* __restrict__ stIn,
                              const float* __restrict__ gamIn, const float* __restrict__ betIn) {
    __shared__ float sSc[256], sSh[256];
    const int tid = threadIdx.x;
    {
        float2 cs = bn_coef(stIn[tid], stIn[256 + tid], gamIn[tid], betIn[tid]);
        sSc[tid] = cs.x; sSh[tid] = cs.y;
    }
    __syncthreads();
    int i = blockIdx.x * 256 + tid;
    if (i < N_V * 64) {
        int col = (i & 63) * 4;
        float4 v = ((const float4*)X)[i];
        v.x = bnr(v.x, sSc[col + 0], sSh[col + 0]);
        v.y = bnr(v.y, sSc[col + 1], sSh[col + 1]);
        v.z = bnr(v.z, sSc[col + 2], sSh[col + 2]);
        v.w = bnr(v.w, sSc[col + 3], sSh[col + 3]);
        ((float4*)desc)[i] = v;
        uint2 hv;
        hv.x = packh(__float2half(v.x), __float2half(v.y));
        hv.y = packh(__float2half(v.z), __float2half(v.w));
        ((uint2*)g_aw)[i] = hv;
    }
}

// ---------------- in-place row log-softmax (float4, FMA-pipe exp) -----------
__global__ void lsm_kernel(float* __restrict__ out) {
    __shared__ float srow[N_V];
    __shared__ float red[256];
    const int row = blockIdx.x, tid = threadIdx.x;
    float4* p4 = (float4*)(out + (size_t)row * N_V);
    float4* s4 = (float4*)srow;
    float m = -1e30f;
    for (int i = tid; i < N_V / 4; i += 256) {
        float4 v = p4[i];
        s4[i] = v;
        m = fmaxf(m, fmaxf(fmaxf(v.x, v.y), fmaxf(v.z, v.w)));
    }
    red[tid] = m;
    __syncthreads();
    for (int st = 128; st > 0; st >>= 1) {
        if (tid < st) red[tid] = fmaxf(red[tid], red[tid + st]);
        __syncthreads();
    }
    m = red[0];
    __syncthreads();
    float s = 0.f;
    for (int i = tid; i < N_V / 4; i += 256) {
        float4 v = s4[i];
        s += fexp(v.x - m) + fexp(v.y - m) + fexp(v.z - m) + fexp(v.w - m);
    }
    red[tid] = s;
    __syncthreads();
    for (int st = 128; st > 0; st >>= 1) {
        if (tid < st) red[tid] += red[tid + st];
        __syncthreads();
    }
    float lse = m + logf(red[0]);
    for (int i = tid; i < N_V / 4; i += 256) {
        float4 v = s4[i];
        v.x -= lse; v.y -= lse; v.z -= lse; v.w -= lse;
        p4[i] = v;
    }
}

// ---------------- host orchestration ----------------------------------------
extern "C" void kernel_launch(void* const* d_in, const int* in_sizes, int n_in,
                              void* d_out, int out_size) {
    const float* x     = (const float*)d_in[0];
    const float* V     = (const float*)d_in[1];
    const float* Dm    = (const float*)d_in[2];
    const float* eigs  = (const float*)d_in[3];
    const float* fc1_w = (const float*)d_in[4];
    const float* bf1_g = (const float*)d_in[6];
    const float* bf1_b = (const float*)d_in[7];
    const float* W1  = (const float*)d_in[8];
    const float* b1g = (const float*)d_in[10];
    const float* b1b = (const float*)d_in[11];
    const float* W2  = (const float*)d_in[12];
    const float* b2g = (const float*)d_in[14];
    const float* b2b = (const float*)d_in[15];
    const float* W3  = (const float*)d_in[16];
    const float* b3g = (const float*)d_in[18];
    const float* b3b = (const float*)d_in[19];
    const float* fc2_w = (const float*)d_in[20];
    const float* bf2_g = (const float*)d_in[22];
    const float* bf2_b = (const float*)d_in[23];
    const float* fc3_w = (const float*)d_in[24];
    const float* fc3_b = (const float*)d_in[25];

    float* out  = (float*)d_out;
    float* desc = out + (size_t)N_V * N_V;   // outputs: [log_softmax | desc]

    float *accA, *accB, *Gc0, *stats;
    cudaGetSymbolAddress((void**)&accA, g_acc);
    cudaGetSymbolAddress((void**)&accB, g_h);
    cudaGetSymbolAddress((void**)&Gc0,  g_Gc0);
    cudaGetSymbolAddress((void**)&stats, g_stats);
    float* c0l[3] = {Gc0 + 4096, Gc0 + 8192, Gc0 + 12288};
    float* st[5];
    for (int i = 0; i < 5; i++) st[i] = stats + i * 512;

    static bool init_done = false;
    if (!init_done) {
        cudaFuncSetAttribute(fc3_kernel, cudaFuncAttributeMaxDynamicSharedMemorySize, SM_TOT);
        cudaFuncSetAttribute(spectral_kernel<64>,  cudaFuncAttributeMaxDynamicSharedMemorySize, (5 * 4096 + 2 * 64 * 64) * 4);
        cudaFuncSetAttribute(spectral_kernel<128>, cudaFuncAttributeMaxDynamicSharedMemorySize, (5 * 4096 + 2 * 64 * 128) * 4);
        cudaFuncSetAttribute(chebout_kernel<64>,  cudaFuncAttributeMaxDynamicSharedMemorySize, 65536);
        cudaFuncSetAttribute(chebout_kernel<128>, cudaFuncAttributeMaxDynamicSharedMemorySize, 98304);
        init_done = true;
    }

    // prep: zero G/c0/stats; G = D @ V; fc3_w transpose+fp16
    zeroall<<<74, 256>>>();
    dmat_kernel<0><<<125, 256>>>(Dm, V, Gc0, nullptr, nullptr, nullptr);
    split_b_kernel<<<dim3((N_V + 31) / 32, 256 / 32), dim3(32, 32)>>>(fc3_w);

    // fc1 -> accA (pre-BN) + stats L0  (BM=32: grid 313, fixes grid starvation)
    {
        dim3 g1(1, (N_V + 31) / 32);
        gemm_small<0, 1, 32><<<g1, 256>>>(x, fc1_w, accA, N_V, 64, IN_DESC,
                                          nullptr, nullptr, nullptr, st[0]);
    }

    // cheb layer 1: BN(accA; L0) -> accB, stats L1
    dmat_kernel<1><<<125, 256>>>(Dm, accA, c0l[0], st[0], bf1_g, bf1_b);
    spectral_kernel<64><<<1, 1024, (5 * 4096 + 2 * 64 * 64) * 4>>>(W1, eigs, c0l[0]);
    chebout_kernel<64><<<(N_V + 63) / 64, 256, 65536>>>(accA, V, accB, st[0], bf1_g, bf1_b, st[1]);

    // cheb layer 2: BN(accB; L1) -> accA, stats L2
    dmat_kernel<1><<<125, 256>>>(Dm, accB, c0l[1], st[1], b1g, b1b);
    spectral_kernel<64><<<1, 1024, (5 * 4096 + 2 * 64 * 64) * 4>>>(W2, eigs, c0l[1]);
    chebout_kernel<64><<<(N_V + 63) / 64, 256, 65536>>>(accB, V, accA, st[1], b1g, b1b, st[2]);

    // cheb layer 3: BN(accA; L2) -> accB (width 128), stats L3
    dmat_kernel<1><<<125, 256>>>(Dm, accA, c0l[2], st[2], b2g, b2b);
    spectral_kernel<128><<<1, 1024, (5 * 4096 + 2 * 64 * 128) * 4>>>(W3, eigs, c0l[2]);
    chebout_kernel<128><<<(N_V + 63) / 64, 256, 98304>>>(accA, V, accB, st[2], b2g, b2b, st[3]);

    // fc2: BN(accB; L3)[128] -> accA (256 wide) + stats L4; fused apply+fp16
    {
        dim3 g2(256 / 64, (N_V + 63) / 64);
        gemm_small<1, 1, 64><<<g2, 256>>>(accB, fc2_w, accA, N_V, 256, 128,
                                          st[3], b3g, b3b, st[4]);
        bn_apply_desc<<<(N_V * 64 + 255) / 256, 256>>>(accA, desc, st[4], bf2_g, bf2_b);
    }

    // fc3 (mma.sync fp16, cp.async pipelined) -> logits
    {
        dim3 g3((N_V + 127) / 128, (N_V + 127) / 128);
        fc3_kernel<<<g3, 256, SM_TOT>>>(fc3_b, out);
    }

    // in-place row log-softmax
    lsm_kernel<<<N_V, 256>>>(out);
}

// round 17
// speedup vs baseline: 1.2186x; 1.2186x over previous
#include <cuda_runtime.h>
#include <cuda_fp16.h>
#include <math.h>
#include <stdint.h>

#define N_V 10000
#define NSPEC 64
#define IN_DESC 352
#define OUT_DESC 256

// ---------------- scratch (device globals; no allocations allowed) ----------
__device__ float g_acc[N_V * 256];   // accA (pre-BN, max width 256)
__device__ float g_h[N_V * 128];     // accB (pre-BN, width <=128)
__device__ float g_Gc0[4 * 4096];    // [G | c0_layer1 | c0_layer2 | c0_layer3]
__device__ float g_stats[5 * 512];   // per-layer [sum(256) | sumsq(256)]
__device__ float g_M[5 * 4096];      // Chebyshev operator polys M1..M5
__device__ float g_Ul[3 * 8192];     // per-layer spectral weight combo U
__device__ float g_Wx[64 * 128];     // direct-X weight combo [64,Cout]
__device__ __half g_bw[N_V * 256];   // fc3_w transposed [N,K] fp16
__device__ __half g_aw[N_V * 256];   // desc [M,K] fp16

// ---------------- mma.sync + cp.async helpers (base sm_103-legal) -----------
__device__ __forceinline__ uint32_t smem_u32(const void* p) {
    uint32_t a;
    asm("{ .reg .u64 t; cvta.to.shared.u64 t, %1; cvt.u32.u64 %0, t; }" : "=r"(a) : "l"(p));
    return a;
}
#define LDSM_X4(r0, r1, r2, r3, addr) \
    asm volatile("ldmatrix.sync.aligned.m8n8.x4.shared.b16 {%0,%1,%2,%3}, [%4];" \
        : "=r"(r0), "=r"(r1), "=r"(r2), "=r"(r3) : "r"(addr))
#define LDSM_X2(r0, r1, addr) \
    asm volatile("ldmatrix.sync.aligned.m8n8.x2.shared.b16 {%0,%1}, [%2];" \
        : "=r"(r0), "=r"(r1) : "r"(addr))
#define MMA_F16(c, a, b) \
    asm volatile("mma.sync.aligned.m16n8k16.row.col.f32.f16.f16.f32 " \
        "{%0,%1,%2,%3}, {%4,%5,%6,%7}, {%8,%9}, {%0,%1,%2,%3};" \
        : "+f"((c)[0]), "+f"((c)[1]), "+f"((c)[2]), "+f"((c)[3]) \
        : "r"((a)[0]), "r"((a)[1]), "r"((a)[2]), "r"((a)[3]), "r"((b)[0]), "r"((b)[1]))
#define CP_ASYNC16(smaddr, gptr) \
    asm volatile("cp.async.cg.shared.global [%0], [%1], 16;" :: "r"(smaddr), "l"(gptr))
#define CP_COMMIT() asm volatile("cp.async.commit_group;" ::: "memory")
#define CP_WAIT1()  asm volatile("cp.async.wait_group 1;" ::: "memory")
#define CP_WAIT0()  asm volatile("cp.async.wait_group 0;" ::: "memory")

__device__ __forceinline__ uint32_t sw128(uint32_t off) {
    return off ^ ((off >> 3) & 0x70);
}
__device__ __forceinline__ uint32_t packh(__half a, __half b) {
    unsigned short ua = *reinterpret_cast<unsigned short*>(&a);
    unsigned short ub = *reinterpret_cast<unsigned short*>(&b);
    return (uint32_t)ua | ((uint32_t)ub << 16);
}
__device__ __forceinline__ float bnr(float x, float sc, float sh) {
    return fmaxf(fmaf(x, sc, sh), 0.f);
}
__device__ __forceinline__ float2 bn_coef(float sum, float sq, float gam, float bet) {
    float mean = sum * (1.f / N_V);
    float var = sq * (1.f / N_V) - mean * mean;
    float sc = gam * rsqrtf(var + 1e-3f);
    return make_float2(sc, bet - mean * sc);
}

// FMA-pipe exp
__device__ __forceinline__ float fexp(float x) {
    float y = fmaxf(x * 1.4426950408889634f, -120.f);
    float fi = floorf(y);
    float f = y - fi;
    float r = 1.5403530e-4f;
    r = fmaf(r, f, 1.3333558e-3f);
    r = fmaf(r, f, 9.6181291e-3f);
    r = fmaf(r, f, 5.5504109e-2f);
    r = fmaf(r, f, 2.4022651e-1f);
    r = fmaf(r, f, 6.9314718e-1f);
    r = fmaf(r, f, 1.0f);
    return __int_as_float(__float_as_int(r) + ((int)fi << 23));
}

// ---------------- zero G/c0 arena + stats + per-layer U ----------------------
__global__ void zeroall() {
    int i = blockIdx.x * 256 + threadIdx.x;
    if (i < 4 * 4096) g_Gc0[i] = 0.f;
    else if (i < 4 * 4096 + 5 * 512) g_stats[i - 4 * 4096] = 0.f;
    else if (i < 4 * 4096 + 5 * 512 + 3 * 8192) g_Ul[i - 4 * 4096 - 5 * 512] = 0.f;
}

// ---------------- fc3_w pre-transpose + fp16 ---------------------------------
__global__ void split_b_kernel(const float* __restrict__ W) {
    __shared__ float s[32][33];
    const int tx = threadIdx.x, ty = threadIdx.y;
    const int n0 = blockIdx.x * 32, k0 = blockIdx.y * 32;
    float v = 0.f;
    if (n0 + tx < N_V) v = W[(size_t)(k0 + ty) * N_V + n0 + tx];
    s[ty][tx] = v;
    __syncthreads();
    int n = n0 + ty;
    if (n < N_V) g_bw[(size_t)n * 256 + k0 + tx] = __float2half(s[tx][ty]);
}

// ---------------- Chebyshev operator polys: M1..M5 (once) --------------------
// M1 = diag(e); M_{k+1} = 2E(G Mk + a_k I) - M_{k-1},  a = {0,-1,0,1} for k=1..4
__global__ void mk_kernel(const float* __restrict__ eigs) {
    extern __shared__ float sm[];
    float* G  = sm;
    float* Mp = G + 4096;
    float* Mc = Mp + 4096;
    float* ck = Mc + 4096;
    __shared__ float e[64];
    const int tid = threadIdx.x;
    const int T = blockDim.x;
    for (int i = tid; i < 4096; i += T) G[i] = g_Gc0[i];
    if (tid < 64) e[tid] = eigs[tid];
    __syncthreads();
    for (int i = tid; i < 4096; i += T) {
        int r = i >> 6, c = i & 63;
        float v = (r == c) ? e[r] : 0.f;
        Mc[i] = v; Mp[i] = 0.f;
        g_M[i] = v;
    }
    __syncthreads();
    for (int k = 1; k <= 4; k++) {
        const float a = (k == 2) ? -1.f : ((k == 4) ? 1.f : 0.f);
        for (int i = tid; i < 4096; i += T) {
            int r = i >> 6, c = i & 63;
            float s = 0.f;
            #pragma unroll
            for (int m = 0; m < 64; m += 4) {
                float4 g4 = *(const float4*)(G + r * 64 + m);
                s += g4.x * Mc[m * 64 + c] + g4.y * Mc[(m + 1) * 64 + c]
                   + g4.z * Mc[(m + 2) * 64 + c] + g4.w * Mc[(m + 3) * 64 + c];
            }
            ck[i] = s + ((r == c) ? a : 0.f);
        }
        __syncthreads();
        for (int i = tid; i < 4096; i += T) {
            float v = 2.f * e[i >> 6] * ck[i] - Mp[i];
            Mp[i] = v;
            g_M[(size_t)k * 4096 + i] = v;
        }
        __syncthreads();
        float* t = Mp; Mp = Mc; Mc = t;
    }
}

// ---------------- per-layer spectral apply: U += (Mk c0) Wk, Wx --------------
// grid = 6: blocks 0..4 handle k, block 5 computes Wx.
template<int COUT>
__global__ void spectral_apply(const float* __restrict__ W,
                               const float* __restrict__ c0g,
                               float* __restrict__ U) {
    const int tid = threadIdx.x;
    if (blockIdx.x == 5) {
        for (int i = tid; i < 64 * COUT; i += 256)
            g_Wx[i] = W[i] - W[2 * 64 * COUT + i] + W[4 * 64 * COUT + i];
        return;
    }
    extern __shared__ float sm[];
    float* M  = sm;
    float* c0 = M + 4096;
    float* s  = c0 + 4096;
    float* sW = s + 4096;
    const int k = blockIdx.x;   // 0..4 -> s_{k+1} with W_{k+1}
    for (int i = tid; i < 4096; i += 256) {
        M[i]  = g_M[(size_t)k * 4096 + i];
        c0[i] = c0g[i];
    }
    for (int i = tid; i < 64 * COUT; i += 256)
        sW[i] = W[(size_t)(k + 1) * 64 * COUT + i];
    __syncthreads();
    for (int i = tid; i < 4096; i += 256) {
        int r = i >> 6, c = i & 63;
        float acc = 0.f;
        #pragma unroll
        for (int m = 0; m < 64; m += 4) {
            float4 m4 = *(const float4*)(M + r * 64 + m);
            acc += m4.x * c0[m * 64 + c] + m4.y * c0[(m + 1) * 64 + c]
                 + m4.z * c0[(m + 2) * 64 + c] + m4.w * c0[(m + 3) * 64 + c];
        }
        s[i] = acc;
    }
    __syncthreads();
    for (int i = tid; i < 64 * COUT; i += 256) {
        int r = i / COUT, c = i % COUT;
        float acc = 0.f;
        #pragma unroll
        for (int m = 0; m < 64; m += 4) {
            float4 s4 = *(const float4*)(s + r * 64 + m);
            acc += s4.x * sW[m * COUT + c] + s4.y * sW[(m + 1) * COUT + c]
                 + s4.z * sW[(m + 2) * COUT + c] + s4.w * sW[(m + 3) * COUT + c];
        }
        atomicAdd(&U[i], acc);
    }
}

// ---------------- fc3 GEMM: mma.sync fp16, cp.async double-buffered ----------
#define SM_A0 0
#define SM_B0 16384
#define SM_A1 32768
#define SM_B1 49152
#define SM_TOT 65536

__global__ __launch_bounds__(256, 2)
void fc3_kernel(const float* __restrict__ bias, float* __restrict__ C) {
    extern __shared__ char smem[];
    const uint32_t sbase = smem_u32(smem);
    const int tid = threadIdx.x;
    const int wid = tid >> 5, lane = tid & 31;
    const int wm = wid >> 2, wn = wid & 3;
    const int row0 = blockIdx.y * 128, col0 = blockIdx.x * 128;

    float acc[4][4][4] = {};

    const int l15 = lane & 15;
    const uint32_t a_row = (uint32_t)(wm * 64 + l15);
    const uint32_t a_halfb = (uint32_t)((lane >> 4) * 16);
    const uint32_t b_row = (uint32_t)(wn * 32 + (l15 & 7));
    const uint32_t b_halfb = (uint32_t)((l15 >> 3) * 16);

    const int lr = tid >> 3, lc = tid & 7;

    auto load_chunk = [&](int kc, int buf) {
        const uint32_t sa = sbase + (buf ? SM_A1 : SM_A0);
        const uint32_t sb = sbase + (buf ? SM_B1 : SM_B0);
        #pragma unroll
        for (int t = 0; t < 4; t++) {
            int r = lr + t * 32;
            uint32_t soff = sw128((uint32_t)(r * 128 + lc * 16));
            int ra = min(row0 + r, N_V - 1);
            const char* ga = (const char*)g_aw + (size_t)ra * 512 + (size_t)kc * 128 + lc * 16;
            CP_ASYNC16(sa + soff, ga);
            int rb = min(col0 + r, N_V - 1);
            const char* gb = (const char*)g_bw + (size_t)rb * 512 + (size_t)kc * 128 + lc * 16;
            CP_ASYNC16(sb + soff, gb);
        }
    };

    load_chunk(0, 0);
    CP_COMMIT();

    #pragma unroll
    for (int kc = 0; kc < 4; kc++) {
        if (kc < 3) {
            load_chunk(kc + 1, (kc + 1) & 1);
            CP_COMMIT();
            CP_WAIT1();
        } else {
            CP_WAIT0();
        }
        __syncthreads();
        const uint32_t sa = sbase + ((kc & 1) ? SM_A1 : SM_A0);
        const uint32_t sb = sbase + ((kc & 1) ? SM_B1 : SM_B0);
        #pragma unroll
        for (int ks = 0; ks < 4; ks++) {
            uint32_t af[4][4], bf[4][2];
            #pragma unroll
            for (int mt = 0; mt < 4; mt++) {
                uint32_t off = sw128((a_row + mt * 16) * 128 + ks * 32 + a_halfb);
                LDSM_X4(af[mt][0], af[mt][1], af[mt][2], af[mt][3], sa + off);
            }
            #pragma unroll
            for (int nt = 0; nt < 4; nt++) {
                uint32_t off = sw128((b_row + nt * 8) * 128 + ks * 32 + b_halfb);
                LDSM_X2(bf[nt][0], bf[nt][1], sb + off);
            }
            #pragma unroll
            for (int mt = 0; mt < 4; mt++)
                #pragma unroll
                for (int nt = 0; nt < 4; nt++)
                    MMA_F16(acc[mt][nt], af[mt], bf[nt]);
        }
        __syncthreads();
    }

    const int r_base = row0 + wm * 64 + (lane >> 2);
    const int c_base = col0 + wn * 32 + ((lane & 3) << 1);
    #pragma unroll
    for (int mt = 0; mt < 4; mt++) {
        #pragma unroll
        for (int nt = 0; nt < 4; nt++) {
            int cc = c_base + nt * 8;
            if (cc >= N_V) continue;
            float2 bb = *(const float2*)(bias + cc);
            int rr = r_base + mt * 16;
            if (rr < N_V) {
                float2 v = make_float2(acc[mt][nt][0] + bb.x, acc[mt][nt][1] + bb.y);
                *(float2*)(C + (size_t)rr * N_V + cc) = v;
            }
            if (rr + 8 < N_V) {
                float2 v = make_float2(acc[mt][nt][2] + bb.x, acc[mt][nt][3] + bb.y);
                *(float2*)(C + (size_t)(rr + 8) * N_V + cc) = v;
            }
        }
    }
}

// ---------------- small GEMM (fc1/fc2): C = BN?(A) @ B, + stats --------------
template<int BNIN, int STATS>
__global__ void gemm_small(const float* __restrict__ A, const float* __restrict__ B,
                           float* __restrict__ C, int M, int Nn, int K,
                           const float* __restrict__ stIn,
                           const float* __restrict__ gamIn, const float* __restrict__ betIn,
                           float* __restrict__ stOut) {
    __shared__ float As[16][64];
    __shared__ float Bs[16][64];
    __shared__ float sSc[128], sSh[128];
    __shared__ float sbuf[64 * 65 + 2 * 4 * 64];
    const int tid = threadIdx.x;
    const int ty = tid >> 4, tx = tid & 15;
    const int row0 = blockIdx.y * 64, col0 = blockIdx.x * 64;
    const int arow = tid >> 2, ak = (tid & 3) << 2;
    const int bk = tid >> 4, bcol = (tid & 15) << 2;
    if (BNIN && tid < 128) {
        float2 cs = bn_coef(stIn[tid], stIn[256 + tid], gamIn[tid], betIn[tid]);
        sSc[tid] = cs.x; sSh[tid] = cs.y;
    }
    if (BNIN) __syncthreads();
    float acc[4][4] = {};
    for (int k0 = 0; k0 < K; k0 += 16) {
        float4 av = make_float4(0.f, 0.f, 0.f, 0.f);
        if (row0 + arow < M)
            av = *(const float4*)(A + (size_t)(row0 + arow) * K + k0 + ak);
        if (BNIN) {
            av.x = bnr(av.x, sSc[k0 + ak + 0], sSh[k0 + ak + 0]);
            av.y = bnr(av.y, sSc[k0 + ak + 1], sSh[k0 + ak + 1]);
            av.z = bnr(av.z, sSc[k0 + ak + 2], sSh[k0 + ak + 2]);
            av.w = bnr(av.w, sSc[k0 + ak + 3], sSh[k0 + ak + 3]);
        }
        As[ak + 0][arow] = av.x; As[ak + 1][arow] = av.y;
        As[ak + 2][arow] = av.z; As[ak + 3][arow] = av.w;
        float4 bv = *(const float4*)(B + (size_t)(k0 + bk) * Nn + col0 + bcol);
        *(float4*)(&Bs[bk][bcol]) = bv;
        __syncthreads();
        #pragma unroll
        for (int kk = 0; kk < 16; kk++) {
            float a[4], b[4];
            #pragma unroll
            for (int i = 0; i < 4; i++) a[i] = As[kk][ty * 4 + i];
            #pragma unroll
            for (int j = 0; j < 4; j++) b[j] = Bs[kk][tx * 4 + j];
            #pragma unroll
            for (int i = 0; i < 4; i++)
                #pragma unroll
                for (int j = 0; j < 4; j++)
                    acc[i][j] += a[i] * b[j];
        }
        __syncthreads();
    }
    #pragma unroll
    for (int i = 0; i < 4; i++) {
        int r = row0 + ty * 4 + i;
        if (r >= M) continue;
        #pragma unroll
        for (int j = 0; j < 4; j++)
            C[(size_t)r * Nn + col0 + tx * 4 + j] = acc[i][j];
    }
    if (STATS) {
        #pragma unroll
        for (int i = 0; i < 4; i++)
            #pragma unroll
            for (int j = 0; j < 4; j++)
                sbuf[(ty * 4 + i) * 65 + tx * 4 + j] = acc[i][j];
        __syncthreads();
        const int c = tid & 63, chunk = tid >> 6;
        float s = 0.f, s2 = 0.f;
        #pragma unroll
        for (int rr = 0; rr < 16; rr++) {
            int r = chunk * 16 + rr;
            if (row0 + r < M) {
                float v = sbuf[r * 65 + c];
                s += v; s2 += v * v;
            }
        }
        float* red = sbuf + 64 * 65;
        red[chunk * 64 + c] = s;
        red[256 + chunk * 64 + c] = s2;
        __syncthreads();
        if (tid < 64) {
            float ts = 0.f, ts2 = 0.f;
            #pragma unroll
            for (int k = 0; k < 4; k++) { ts += red[k * 64 + tid]; ts2 += red[256 + k * 64 + tid]; }
            atomicAdd(&stOut[col0 + tid], ts);
            atomicAdd(&stOut[256 + col0 + tid], ts2);
        }
    }
}

// ---------------- 64x64 split-K reduce: out += D @ BN?(Z) --------------------
template<int BNIN>
__global__ void dmat_kernel(const float* __restrict__ Dm, const float* __restrict__ Z,
                            float* __restrict__ outp,
                            const float* __restrict__ stIn,
                            const float* __restrict__ gamIn, const float* __restrict__ betIn) {
    __shared__ float sD[4][64];
    __shared__ float sZ[4][64];
    const int tid = threadIdx.x;
    const int i4 = (tid >> 4) << 2;
    const int j4 = (tid & 15) << 2;
    const int zc = tid & 63;
    float zsc = 0.f, zsh = 0.f;
    if (BNIN) {
        float2 cs = bn_coef(stIn[zc], stIn[256 + zc], gamIn[zc], betIn[zc]);
        zsc = cs.x; zsh = cs.y;
    }
    float acc[4][4] = {};
    const int nb0 = blockIdx.x * 80;
    for (int nb = 0; nb < 80; nb += 4) {
        const int nbase = nb0 + nb;
        {
            int ii = tid >> 2, nn = tid & 3;
            sD[nn][ii] = Dm[(size_t)ii * N_V + nbase + nn];
            float z = Z[(size_t)(nbase + (tid >> 6)) * 64 + zc];
            if (BNIN) z = bnr(z, zsc, zsh);
            sZ[tid >> 6][zc] = z;
        }
        __syncthreads();
        #pragma unroll
        for (int nn = 0; nn < 4; nn++) {
            float d[4], z[4];
            #pragma unroll
            for (int a = 0; a < 4; a++) d[a] = sD[nn][i4 + a];
            #pragma unroll
            for (int b = 0; b < 4; b++) z[b] = sZ[nn][j4 + b];
            #pragma unroll
            for (int a = 0; a < 4; a++)
                #pragma unroll
                for (int b = 0; b < 4; b++)
                    acc[a][b] += d[a] * z[b];
        }
        __syncthreads();
    }
    #pragma unroll
    for (int a = 0; a < 4; a++)
        #pragma unroll
        for (int b = 0; b < 4; b++)
            atomicAdd(&outp[(i4 + a) * 64 + j4 + b], acc[a][b]);
}

// ---------------- cheb output: out = BN(X) @ Wx + V @ U, + stats -------------
template<int COUT>
__global__ void chebout_kernel(const float* __restrict__ X, const float* __restrict__ Vm,
                               float* __restrict__ outp,
                               const float* __restrict__ stIn,
                               const float* __restrict__ gamIn, const float* __restrict__ betIn,
                               float* __restrict__ stOut,
                               const float* __restrict__ Uin) {
    constexpr int TPR = COUT / 32;
    constexpr int ROWS = 256 / TPR;
    constexpr int CH = 256 / COUT;
    constexpr int STRIDE = COUT + 1;
    extern __shared__ float sm[];
    float* sWx = sm;
    float* sU  = sWx + 64 * COUT;
    float* sX  = sU + 64 * COUT;
    float* sV  = sX + ROWS * 64;
    __shared__ float sSc[64], sSh[64];
    const int tid = threadIdx.x;
    if (tid < 64) {
        float2 cs = bn_coef(stIn[tid], stIn[256 + tid], gamIn[tid], betIn[tid]);
        sSc[tid] = cs.x; sSh[tid] = cs.y;
    }
    __syncthreads();
    for (int i = tid; i < 64 * COUT; i += 256) { sWx[i] = g_Wx[i]; sU[i] = Uin[i]; }
    const int row0 = blockIdx.x * ROWS;
    for (int i = tid; i < ROWS * 16; i += 256) {
        int r = i >> 4, q = i & 15;
        int gr = row0 + r;
        float4 xv = make_float4(0.f, 0.f, 0.f, 0.f), vv = xv;
        if (gr < N_V) {
            xv = *(const float4*)(X + (size_t)gr * 64 + q * 4);
            vv = *(const float4*)(Vm + (size_t)gr * 64 + q * 4);
            xv.x = bnr(xv.x, sSc[q * 4 + 0], sSh[q * 4 + 0]);
            xv.y = bnr(xv.y, sSc[q * 4 + 1], sSh[q * 4 + 1]);
            xv.z = bnr(xv.z, sSc[q * 4 + 2], sSh[q * 4 + 2]);
            xv.w = bnr(xv.w, sSc[q * 4 + 3], sSh[q * 4 + 3]);
        }
        *(float4*)(sX + r * 64 + q * 4) = xv;
        *(float4*)(sV + r * 64 + q * 4) = vv;
    }
    __syncthreads();
    const int lr = tid / TPR;
    const int j0 = (tid % TPR) * 32;
    const int gr = row0 + lr;
    float acc[32] = {};
    #pragma unroll 4
    for (int k = 0; k < 64; k++) {
        float a = sX[lr * 64 + k];
        #pragma unroll
        for (int j = 0; j < 32; j++) acc[j] += a * sWx[k * COUT + j0 + j];
    }
    #pragma unroll 4
    for (int k = 0; k < 64; k++) {
        float v = sV[lr * 64 + k];
        #pragma unroll
        for (int j = 0; j < 32; j++) acc[j] += v * sU[k * COUT + j0 + j];
    }
    if (gr < N_V) {
        float* o = outp + (size_t)gr * COUT + j0;
        #pragma unroll
        for (int j = 0; j < 32; j++) o[j] = acc[j];
    }
    __syncthreads();
    float* sbuf = sm;
    #pragma unroll
    for (int j = 0; j < 32; j++) sbuf[lr * STRIDE + j0 + j] = acc[j];
    __syncthreads();
    {
        const int c = tid % COUT, chunk = tid / COUT;
        constexpr int RPC = ROWS / CH;
        float s = 0.f, s2 = 0.f;
        #pragma unroll
        for (int rr = 0; rr < RPC; rr++) {
            int r = chunk * RPC + rr;
            if (row0 + r < N_V) {
                float v = sbuf[r * STRIDE + c];
                s += v; s2 += v * v;
            }
        }
        float* red = sbuf + ROWS * STRIDE;
        red[chunk * COUT + c] = s;
        red[CH * COUT + chunk * COUT + c] = s2;
        __syncthreads();
        if (tid < COUT) {
            float ts = 0.f, ts2 = 0.f;
            #pragma unroll
            for (int k = 0; k < CH; k++) {
                ts += red[k * COUT + tid];
                ts2 += red[CH * COUT + k * COUT + tid];
            }
            atomicAdd(&stOut[tid], ts);
            atomicAdd(&stOut[256 + tid], ts2);
        }
    }
}

// ---------------- final BN apply -> desc fp32 + fp16 -------------------------
__global__ void bn_apply_desc(const float* __restrict__ X, float* __restrict__ desc,
                              const float* __restrict__ stIn,
                              const float* __restrict__ gamIn, const float* __restrict__ betIn) {
    __shared__ float sSc[256], sSh[256];
    const int tid = threadIdx.x;
    {
        float2 cs = bn_coef(stIn[tid], stIn[256 + tid], gamIn[tid], betIn[tid]);
        sSc[tid] = cs.x; sSh[tid] = cs.y;
    }
    __syncthreads();
    int i = blockIdx.x * 256 + tid;
    if (i < N_V * 64) {
        int col = (i & 63) * 4;
        float4 v = ((const float4*)X)[i];
        v.x = bnr(v.x, sSc[col + 0], sSh[col + 0]);
        v.y = bnr(v.y, sSc[col + 1], sSh[col + 1]);
        v.z = bnr(v.z, sSc[col + 2], sSh[col + 2]);
        v.w = bnr(v.w, sSc[col + 3], sSh[col + 3]);
        ((float4*)desc)[i] = v;
        uint2 hv;
        hv.x = packh(__float2half(v.x), __float2half(v.y));
        hv.y = packh(__float2half(v.z), __float2half(v.w));
        ((uint2*)g_aw)[i] = hv;
    }
}

// ---------------- in-place row log-softmax (float4, FMA-pipe exp) -----------
__global__ void lsm_kernel(float* __restrict__ out) {
    __shared__ float srow[N_V];
    __shared__ float red[256];
    const int row = blockIdx.x, tid = threadIdx.x;
    float4* p4 = (float4*)(out + (size_t)row * N_V);
    float4* s4 = (float4*)srow;
    float m = -1e30f;
    for (int i = tid; i < N_V / 4; i += 256) {
        float4 v = p4[i];
        s4[i] = v;
        m = fmaxf(m, fmaxf(fmaxf(v.x, v.y), fmaxf(v.z, v.w)));
    }
    red[tid] = m;
    __syncthreads();
    for (int st = 128; st > 0; st >>= 1) {
        if (tid < st) red[tid] = fmaxf(red[tid], red[tid + st]);
        __syncthreads();
    }
    m = red[0];
    __syncthreads();
    float s = 0.f;
    for (int i = tid; i < N_V / 4; i += 256) {
        float4 v = s4[i];
        s += fexp(v.x - m) + fexp(v.y - m) + fexp(v.z - m) + fexp(v.w - m);
    }
    red[tid] = s;
    __syncthreads();
    for (int st = 128; st > 0; st >>= 1) {
        if (tid < st) red[tid] += red[tid + st];
        __syncthreads();
    }
    float lse = m + logf(red[0]);
    for (int i = tid; i < N_V / 4; i += 256) {
        float4 v = s4[i];
        v.x -= lse; v.y -= lse; v.z -= lse; v.w -= lse;
        p4[i] = v;
    }
}

// ---------------- host orchestration ----------------------------------------
extern "C" void kernel_launch(void* const* d_in, const int* in_sizes, int n_in,
                              void* d_out, int out_size) {
    const float* x     = (const float*)d_in[0];
    const float* V     = (const float*)d_in[1];
    const float* Dm    = (const float*)d_in[2];
    const float* eigs  = (const float*)d_in[3];
    const float* fc1_w = (const float*)d_in[4];
    const float* bf1_g = (const float*)d_in[6];
    const float* bf1_b = (const float*)d_in[7];
    const float* W1  = (const float*)d_in[8];
    const float* b1g = (const float*)d_in[10];
    const float* b1b = (const float*)d_in[11];
    const float* W2  = (const float*)d_in[12];
    const float* b2g = (const float*)d_in[14];
    const float* b2b = (const float*)d_in[15];
    const float* W3  = (const float*)d_in[16];
    const float* b3g = (const float*)d_in[18];
    const float* b3b = (const float*)d_in[19];
    const float* fc2_w = (const float*)d_in[20];
    const float* bf2_g = (const float*)d_in[22];
    const float* bf2_b = (const float*)d_in[23];
    const float* fc3_w = (const float*)d_in[24];
    const float* fc3_b = (const float*)d_in[25];

    float* out  = (float*)d_out;
    float* desc = out + (size_t)N_V * N_V;   // outputs: [log_softmax | desc]

    float *accA, *accB, *Gc0, *stats, *Ul;
    cudaGetSymbolAddress((void**)&accA, g_acc);
    cudaGetSymbolAddress((void**)&accB, g_h);
    cudaGetSymbolAddress((void**)&Gc0,  g_Gc0);
    cudaGetSymbolAddress((void**)&stats, g_stats);
    cudaGetSymbolAddress((void**)&Ul, g_Ul);
    float* c0l[3] = {Gc0 + 4096, Gc0 + 8192, Gc0 + 12288};
    float* st[5];
    for (int i = 0; i < 5; i++) st[i] = stats + i * 512;
    float* ul[3] = {Ul, Ul + 8192, Ul + 16384};

    static bool init_done = false;
    if (!init_done) {
        cudaFuncSetAttribute(fc3_kernel, cudaFuncAttributeMaxDynamicSharedMemorySize, SM_TOT);
        cudaFuncSetAttribute(mk_kernel, cudaFuncAttributeMaxDynamicSharedMemorySize, 65536);
        cudaFuncSetAttribute(spectral_apply<64>,  cudaFuncAttributeMaxDynamicSharedMemorySize, (3 * 4096 + 64 * 64) * 4);
        cudaFuncSetAttribute(spectral_apply<128>, cudaFuncAttributeMaxDynamicSharedMemorySize, (3 * 4096 + 64 * 128) * 4);
        cudaFuncSetAttribute(chebout_kernel<64>,  cudaFuncAttributeMaxDynamicSharedMemorySize, 98304);
        cudaFuncSetAttribute(chebout_kernel<128>, cudaFuncAttributeMaxDynamicSharedMemorySize, 98304);
        init_done = true;
    }

    // prep: zero arenas; G = D @ V; Chebyshev operator polys; fc3_w split
    zeroall<<<170, 256>>>();
    dmat_kernel<0><<<125, 256>>>(Dm, V, Gc0, nullptr, nullptr, nullptr);
    mk_kernel<<<1, 1024, 65536>>>(eigs);
    split_b_kernel<<<dim3((N_V + 31) / 32, 256 / 32), dim3(32, 32)>>>(fc3_w);

    // fc1 -> accA (pre-BN) + stats L0
    {
        dim3 g1(1, (N_V + 63) / 64);
        gemm_small<0, 1><<<g1, 256>>>(x, fc1_w, accA, N_V, 64, IN_DESC,
                                      nullptr, nullptr, nullptr, st[0]);
    }

    // cheb layer 1: BN(accA; L0) -> accB, stats L1
    dmat_kernel<1><<<125, 256>>>(Dm, accA, c0l[0], st[0], bf1_g, bf1_b);
    spectral_apply<64><<<6, 256, (3 * 4096 + 64 * 64) * 4>>>(W1, c0l[0], ul[0]);
    chebout_kernel<64><<<(N_V + 127) / 128, 256, 98304>>>(accA, V, accB, st[0], bf1_g, bf1_b, st[1], ul[0]);

    // cheb layer 2: BN(accB; L1) -> accA, stats L2
    dmat_kernel<1><<<125, 256>>>(Dm, accB, c0l[1], st[1], b1g, b1b);
    spectral_apply<64><<<6, 256, (3 * 4096 + 64 * 64) * 4>>>(W2, c0l[1], ul[1]);
    chebout_kernel<64><<<(N_V + 127) / 128, 256, 98304>>>(accB, V, accA, st[1], b1g, b1b, st[2], ul[1]);

    // cheb layer 3: BN(accA; L2) -> accB (width 128), stats L3
    dmat_kernel<1><<<125, 256>>>(Dm, accA, c0l[2], st[2], b2g, b2b);
    spectral_apply<128><<<6, 256, (3 * 4096 + 64 * 128) * 4>>>(W3, c0l[2], ul[2]);
    chebout_kernel<128><<<(N_V + 63) / 64, 256, 98304>>>(accA, V, accB, st[2], b2g, b2b, st[3], ul[2]);

    // fc2: BN(accB; L3)[128] -> accA (256 wide) + stats L4; fused apply+fp16
    {
        dim3 g2(256 / 64, (N_V + 63) / 64);
        gemm_small<1, 1><<<g2, 256>>>(accB, fc2_w, accA, N_V, 256, 128,
                                      st[3], b3g, b3b, st[4]);
        bn_apply_desc<<<(N_V * 64 + 255) / 256, 256>>>(accA, desc, st[4], bf2_g, bf2_b);
    }

    // fc3 (mma.sync fp16, cp.async pipelined) -> logits
    {
        dim3 g3((N_V + 127) / 128, (N_V + 127) / 128);
        fc3_kernel<<<g3, 256, SM_TOT>>>(fc3_b, out);
    }

    // in-place row log-softmax
    lsm_kernel<<<N_V, 256>>>(out);
}